// round 1
// baseline (speedup 1.0000x reference)
#include <cuda_runtime.h>
#include <math.h>

#define B_   1024
#define T_   200
#define H_   128
#define G_   384          // 3*H
#define M_   (B_*T_)      // 204800
#define HID1_ 80
#define HID2_ 40

// -------- scratch (device globals: allocation-free contract) --------
__device__ float g_gi[(size_t)M_ * G_];     // 300 MB, reused by both gi GEMMs
__device__ float g_int[(size_t)M_ * H_];    // 100 MB, interests [B,T,H]
__device__ float g_sc[M_];                  // attention scores [B,T]

__device__ __forceinline__ float sigf(float x) { return 1.0f / (1.0f + __expf(-x)); }

// =====================================================================
// GEMM: g_gi[M,384] = A[M,128] @ W[384,128]^T + bias[384]
// A = keys (param) or g_int (useGlobalA). 64x64x16 tiles, 4x4/thread.
// =====================================================================
__global__ void __launch_bounds__(256) gemm_gi(const float* __restrict__ Ap,
                                               const float* __restrict__ W,
                                               const float* __restrict__ bias,
                                               int useGlobalA) {
    const float* __restrict__ A = useGlobalA ? (const float*)g_int : Ap;
    __shared__ float As[16][64];
    __shared__ float Ws[16][64];

    const int tid = threadIdx.x;
    const int m0 = blockIdx.y * 64;
    const int n0 = blockIdx.x * 64;
    const int lr = tid >> 2;            // 0..63
    const int lc = (tid & 3) << 2;      // 0,4,8,12
    const int tm = (tid >> 4) << 2;     // 0..60
    const int tn = (tid & 15) << 2;     // 0..60

    float acc[4][4];
#pragma unroll
    for (int i = 0; i < 4; i++)
#pragma unroll
        for (int j = 0; j < 4; j++) acc[i][j] = 0.f;

#pragma unroll
    for (int k0 = 0; k0 < 128; k0 += 16) {
        float4 av = *(const float4*)&A[(size_t)(m0 + lr) * 128 + k0 + lc];
        float4 wv = *(const float4*)&W[(n0 + lr) * 128 + k0 + lc];
        As[lc + 0][lr] = av.x; As[lc + 1][lr] = av.y;
        As[lc + 2][lr] = av.z; As[lc + 3][lr] = av.w;
        Ws[lc + 0][lr] = wv.x; Ws[lc + 1][lr] = wv.y;
        Ws[lc + 2][lr] = wv.z; Ws[lc + 3][lr] = wv.w;
        __syncthreads();
#pragma unroll
        for (int k = 0; k < 16; k++) {
            float4 a = *(const float4*)&As[k][tm];
            float4 b = *(const float4*)&Ws[k][tn];
            float ar[4] = {a.x, a.y, a.z, a.w};
            float br[4] = {b.x, b.y, b.z, b.w};
#pragma unroll
            for (int i = 0; i < 4; i++)
#pragma unroll
                for (int j = 0; j < 4; j++) acc[i][j] += ar[i] * br[j];
        }
        __syncthreads();
    }

#pragma unroll
    for (int i = 0; i < 4; i++) {
        float4 r;
        r.x = acc[i][0] + bias[n0 + tn + 0];
        r.y = acc[i][1] + bias[n0 + tn + 1];
        r.z = acc[i][2] + bias[n0 + tn + 2];
        r.w = acc[i][3] + bias[n0 + tn + 3];
        *(float4*)&g_gi[(size_t)(m0 + tm + i) * G_ + n0 + tn] = r;
    }
}

// =====================================================================
// Persistent scan: 1 CTA = 8 batch rows, 384 threads (one per gate output),
// Whh^T resident in smem (192 KB). MODE 0: GRU (writes interests).
// MODE 1: AUGRU (uses scores, writes final hidden to out).
// =====================================================================
template <int MODE>
__global__ void __launch_bounds__(384) scan_kernel(const float* __restrict__ Whh,
                                                   const float* __restrict__ bhh,
                                                   const int* __restrict__ lens,
                                                   float* __restrict__ out) {
    extern __shared__ float sm[];
    float* WT = sm;                    // [128][384]  WT[k*384+g] = Whh[g*128+k]
    float* hS = sm + 128 * 384;        // [128][8]    hS[k*8+r]
    float* gS = hS + 128 * 8;          // [384][8]    gS[g*8+r]
    __shared__ int lenS[8];

    const int tid = threadIdx.x;       // == gate output index g
    const int b0 = blockIdx.x * 8;

    for (int i = tid; i < 128 * 384; i += 384) {
        int g = i >> 7, k = i & 127;
        WT[k * 384 + g] = Whh[i];
    }
    for (int i = tid; i < 1024; i += 384) hS[i] = 0.f;
    if (tid < 8) lenS[tid] = lens[b0 + tid];
    const float bg = bhh[tid];
    __syncthreads();

    for (int t = 0; t < T_; t++) {
        // ---- phase 1: gh[g][r] = bhh[g] + sum_k Whh[g][k] * h[r][k]
        float a0 = bg, a1 = bg, a2 = bg, a3 = bg, a4 = bg, a5 = bg, a6 = bg, a7 = bg;
#pragma unroll 4
        for (int k = 0; k < 128; k++) {
            float w = WT[k * 384 + tid];
            float4 hA = *(const float4*)&hS[k * 8];
            float4 hB = *(const float4*)&hS[k * 8 + 4];
            a0 += w * hA.x; a1 += w * hA.y; a2 += w * hA.z; a3 += w * hA.w;
            a4 += w * hB.x; a5 += w * hB.y; a6 += w * hB.z; a7 += w * hB.w;
        }
        *(float4*)&gS[tid * 8]     = make_float4(a0, a1, a2, a3);
        *(float4*)&gS[tid * 8 + 4] = make_float4(a4, a5, a6, a7);
        __syncthreads();

        // ---- phase 2: gate math, 1024 items = 8 rows x 128 dims
#pragma unroll
        for (int it = 0; it < 3; it++) {
            int item = it * 384 + tid;
            if (item < 1024) {
                int r = item >> 7, j = item & 127;
                int base = ((b0 + r) * T_ + t) * G_;
                float ir  = g_gi[base + j];
                float iz  = g_gi[base + 128 + j];
                float in_ = g_gi[base + 256 + j];
                float hr = gS[j * 8 + r];
                float hz = gS[(j + 128) * 8 + r];
                float hn = gS[(j + 256) * 8 + r];
                float hp = hS[j * 8 + r];
                bool valid = (t < lenS[r]);

                float rg = sigf(ir + hr);
                float n  = tanhf(in_ + rg * hn);
                float hnew;
                if (MODE == 0) {
                    float z = sigf(iz + hz);
                    hnew = valid ? ((1.f - z) * n + z * hp) : hp;
                    g_int[((b0 + r) * T_ + t) * H_ + j] = valid ? hnew : 0.f;
                } else {
                    float a = g_sc[(b0 + r) * T_ + t];
                    float u = sigf(iz + hz) * a;
                    hnew = valid ? ((1.f - u) * hp + u * n) : hp;
                }
                hS[j * 8 + r] = hnew;
            }
        }
        __syncthreads();
    }

    if (MODE == 1) {
#pragma unroll
        for (int it = 0; it < 3; it++) {
            int item = it * 384 + tid;
            if (item < 1024) {
                int r = item >> 7, j = item & 127;
                out[(b0 + r) * H_ + j] = hS[j * 8 + r];
            }
        }
    }
}

// =====================================================================
// Attention: 1 CTA per batch b. Builds per-b effective first-layer weight
//   Weff[j][k] = (W1[j,H+k] - W1[j,2H+k]) + q[k]*W1[j,3H+k]
//   cq[j]      = b1[j] + sum_k q[k]*(W1[j,k] + W1[j,2H+k])
// then each thread owns one timestep t: MLP 128->80->40->1, fused softmax.
// =====================================================================
__global__ void __launch_bounds__(256) attn_kernel(const float* __restrict__ q,
                                                   const int* __restrict__ lens,
                                                   const float* __restrict__ W1,
                                                   const float* __restrict__ b1,
                                                   const float* __restrict__ W2,
                                                   const float* __restrict__ b2,
                                                   const float* __restrict__ Wf,
                                                   const float* __restrict__ bf) {
    extern __shared__ float sm[];
    float* Weff = sm;                          // 80*128 = 10240
    float* xS   = Weff + 10240;                // 200*132 = 26400 (pad 132 for alignment)
    float* W2s  = xS + 26400;                  // 40*80 = 3200
    float* cq   = W2s + 3200;                  // 80
    float* b2s  = cq + 80;                     // 40
    float* Wfs  = b2s + 40;                    // 40
    float* qs   = Wfs + 40;                    // 128
    float* lg   = qs + 128;                    // 256
    float* red  = lg + 256;                    // 32

    const int tid = threadIdx.x;
    const int b = blockIdx.x;

    if (tid < 128) qs[tid] = q[b * 128 + tid];
    for (int i = tid; i < 3200; i += 256) W2s[i] = W2[i];
    if (tid < 40) { b2s[tid] = b2[tid]; Wfs[tid] = Wf[tid]; }
    __syncthreads();

    for (int i = tid; i < 10240; i += 256) {
        int j = i >> 7, k = i & 127;
        const float* w1r = &W1[j * 512];
        Weff[i] = w1r[128 + k] - w1r[256 + k] + qs[k] * w1r[384 + k];
    }
    if (tid < 80) {
        const float* w1r = &W1[tid * 512];
        float s0 = 0.f, s1 = 0.f;
        for (int k = 0; k < 128; k += 2) {
            s0 += qs[k]     * (w1r[k]     + w1r[256 + k]);
            s1 += qs[k + 1] * (w1r[k + 1] + w1r[256 + k + 1]);
        }
        cq[tid] = b1[tid] + s0 + s1;
    }
    for (int i = tid; i < 200 * 128; i += 256) {
        int t = i >> 7, k = i & 127;
        xS[t * 132 + k] = g_int[((size_t)b * T_ + t) * H_ + k];
    }
    __syncthreads();

    const int len = lens[b];
    const int t = tid;
    float myLogit = -3.0e38f;

    if (t < T_) {
        float acc2[HID2_];
#pragma unroll
        for (int o = 0; o < HID2_; o++) acc2[o] = 0.f;
        const float* xp = &xS[t * 132];
        for (int j = 0; j < HID1_; j++) {
            const float* wp = &Weff[j * 128];
            float d0 = 0.f, d1 = 0.f, d2 = 0.f, d3 = 0.f;
#pragma unroll
            for (int k = 0; k < 128; k += 4) {
                float4 wv = *(const float4*)&wp[k];
                float4 xv = *(const float4*)&xp[k];
                d0 += wv.x * xv.x; d1 += wv.y * xv.y;
                d2 += wv.z * xv.z; d3 += wv.w * xv.w;
            }
            float s = sigf((d0 + d1) + (d2 + d3) + cq[j]);
#pragma unroll
            for (int o = 0; o < HID2_; o++) acc2[o] += W2s[o * 80 + j] * s;
        }
        float l = bf[0];
#pragma unroll
        for (int o = 0; o < HID2_; o++) l += Wfs[o] * sigf(acc2[o] + b2s[o]);
        l *= 0.08838834764831845f;  // 1/sqrt(128)
        myLogit = (t < len) ? l : -3.0e38f;
    }
    lg[tid] = myLogit;
    __syncthreads();

    // block max
    float v = lg[tid];
#pragma unroll
    for (int off = 16; off; off >>= 1) v = fmaxf(v, __shfl_xor_sync(0xffffffffu, v, off));
    if ((tid & 31) == 0) red[tid >> 5] = v;
    __syncthreads();
    float mx = red[0];
#pragma unroll
    for (int i = 1; i < 8; i++) mx = fmaxf(mx, red[i]);
    __syncthreads();  // everyone done reading red before reuse

    float e = 0.f;
    if (t < T_ && t < len) e = __expf(myLogit - mx);
    v = e;
#pragma unroll
    for (int off = 16; off; off >>= 1) v += __shfl_xor_sync(0xffffffffu, v, off);
    if ((tid & 31) == 0) red[tid >> 5] = v;
    __syncthreads();
    float S = 0.f;
#pragma unroll
    for (int i = 0; i < 8; i++) S += red[i];

    if (t < T_) g_sc[b * T_ + t] = e / S;
}

// =====================================================================
extern "C" void kernel_launch(void* const* d_in, const int* in_sizes, int n_in,
                              void* d_out, int out_size) {
    const float* query = (const float*)d_in[0];
    const float* keys  = (const float*)d_in[1];
    const int*   lens  = (const int*)d_in[2];
    const float* Wih_e = (const float*)d_in[3];
    const float* Whh_e = (const float*)d_in[4];
    const float* bih_e = (const float*)d_in[5];
    const float* bhh_e = (const float*)d_in[6];
    const float* Wih_a = (const float*)d_in[7];
    const float* Whh_a = (const float*)d_in[8];
    const float* bih_a = (const float*)d_in[9];
    const float* bhh_a = (const float*)d_in[10];
    const float* W1 = (const float*)d_in[11];
    const float* b1 = (const float*)d_in[12];
    const float* W2 = (const float*)d_in[13];
    const float* b2 = (const float*)d_in[14];
    const float* Wf = (const float*)d_in[15];
    const float* bf = (const float*)d_in[16];
    float* out = (float*)d_out;

    const int SCAN_SMEM = (128 * 384 + 128 * 8 + 384 * 8) * 4;  // 212992 B
    const int ATT_SMEM  = (10240 + 26400 + 3200 + 80 + 40 + 40 + 128 + 256 + 32) * 4;

    cudaFuncSetAttribute(scan_kernel<0>, cudaFuncAttributeMaxDynamicSharedMemorySize, SCAN_SMEM);
    cudaFuncSetAttribute(scan_kernel<1>, cudaFuncAttributeMaxDynamicSharedMemorySize, SCAN_SMEM);
    cudaFuncSetAttribute(attn_kernel,    cudaFuncAttributeMaxDynamicSharedMemorySize, ATT_SMEM);

    dim3 ggrid(G_ / 64, M_ / 64);  // (6, 3200)

    // 1) gi_e = keys @ Wih_e^T + bih_e
    gemm_gi<<<ggrid, 256>>>(keys, Wih_e, bih_e, 0);
    // 2) GRU scan -> interests
    scan_kernel<0><<<B_ / 8, 384, SCAN_SMEM>>>(Whh_e, bhh_e, lens, nullptr);
    // 3) DIN attention -> scores
    attn_kernel<<<B_, 256, ATT_SMEM>>>(query, lens, W1, b1, W2, b2, Wf, bf);
    // 4) gi_a = interests @ Wih_a^T + bih_a
    gemm_gi<<<ggrid, 256>>>(nullptr, Wih_a, bih_a, 1);
    // 5) AUGRU scan -> out [B,H]
    scan_kernel<1><<<B_ / 8, 384, SCAN_SMEM>>>(Whh_a, bhh_a, lens, out);
}